// round 5
// baseline (speedup 1.0000x reference)
#include <cuda_runtime.h>
#include <math.h>

#define NBATCH   64
#define TSTEPS   512
#define VDIM     512
#define HDIM     256
#define ODIM     512
#define BT_TOTAL (NBATCH * TSTEPS)   // 32768

// Scratch (device globals: no allocation allowed)
__device__ float g_xproj[(size_t)BT_TOTAL * HDIM];  // x @ W_ih^T + b_ih
__device__ float g_hcap [(size_t)BT_TOTAL * HDIM];  // min(h_t, 1) (capped lrelu of relu output)

// ---------------------------------------------------------------------------
// NT SGEMM: C[M,N] = A[M,K] * B[N,K]^T + bias, optional sigmoid.
// BM=128, BN=64, BK=16, 256 threads, 8x4 per-thread tile.
// ---------------------------------------------------------------------------
template<int N, int K, bool SIG>
__global__ __launch_bounds__(256) void gemm_nt_kernel(
    const float* __restrict__ A, const float* __restrict__ Bw,
    const float* __restrict__ bias, float* __restrict__ C)
{
    __shared__ float As[16][128];
    __shared__ float Bs[16][64];
    const int tid = threadIdx.x;
    const int tx = tid & 15;      // n: 16 * 4 = 64
    const int ty = tid >> 4;      // m: 16 * 8 = 128
    const int m0 = blockIdx.y * 128;
    const int n0 = blockIdx.x * 64;

    float acc[8][4];
#pragma unroll
    for (int i = 0; i < 8; i++)
#pragma unroll
        for (int j = 0; j < 4; j++) acc[i][j] = 0.f;

    for (int kt = 0; kt < K; kt += 16) {
#pragma unroll
        for (int i = 0; i < 2; i++) {
            int idx = tid + i * 256;          // 512 float4 = 128x16 floats
            int m = idx >> 2, kq = idx & 3;
            float4 f = *(const float4*)(A + (size_t)(m0 + m) * K + kt + kq * 4);
            As[kq*4+0][m] = f.x; As[kq*4+1][m] = f.y;
            As[kq*4+2][m] = f.z; As[kq*4+3][m] = f.w;
        }
        {
            int n = tid >> 2, kq = tid & 3;   // 256 float4 = 64x16 floats
            float4 f = *(const float4*)(Bw + (size_t)(n0 + n) * K + kt + kq * 4);
            Bs[kq*4+0][n] = f.x; Bs[kq*4+1][n] = f.y;
            Bs[kq*4+2][n] = f.z; Bs[kq*4+3][n] = f.w;
        }
        __syncthreads();
#pragma unroll
        for (int k = 0; k < 16; k++) {
            float4 a0 = *(const float4*)&As[k][ty*8];
            float4 a1 = *(const float4*)&As[k][ty*8+4];
            float4 b4 = *(const float4*)&Bs[k][tx*4];
            float av[8] = {a0.x,a0.y,a0.z,a0.w,a1.x,a1.y,a1.z,a1.w};
            float bv[4] = {b4.x,b4.y,b4.z,b4.w};
#pragma unroll
            for (int i = 0; i < 8; i++)
#pragma unroll
                for (int j = 0; j < 4; j++)
                    acc[i][j] += av[i] * bv[j];
        }
        __syncthreads();
    }

    float4 bvec = *(const float4*)(bias + n0 + tx*4);
    float bb[4] = {bvec.x, bvec.y, bvec.z, bvec.w};
#pragma unroll
    for (int i = 0; i < 8; i++) {
        int m = m0 + ty*8 + i;
        float v[4];
#pragma unroll
        for (int j = 0; j < 4; j++) {
            float x = acc[i][j] + bb[j];
            if (SIG) x = 1.f / (1.f + expf(-x));
            v[j] = x;
        }
        float4 r; r.x=v[0]; r.y=v[1]; r.z=v[2]; r.w=v[3];
        *(float4*)(C + (size_t)m * N + n0 + tx*4) = r;
    }
}

// ---------------------------------------------------------------------------
// Recurrence: one CTA per batch, 512 threads. Thread pair (r, hf) computes
// output row r, k-range [hf*128, hf*128+128): first 48 k's via SMEM-resident
// W columns, remaining 80 via per-thread register-resident W. Shuffle-reduce
// the pair, relu, double-buffered h in SMEM, capped value streamed to g_hcap.
// ---------------------------------------------------------------------------
__global__ __launch_bounds__(512) void rnn_recurrence_kernel(
    const float* __restrict__ prev_state,
    const float* __restrict__ W_hh,
    const float* __restrict__ b_hh,
    float* __restrict__ hn_out)
{
    extern __shared__ float sm[];
    float* Ws  = sm;               // [96][256] : jp<48 -> k=jp (half 0), jp>=48 -> k=128+(jp-48)
    float* hb0 = sm + 96*256;      // h buffers, 256 floats each
    float* hb1 = hb0 + 256;

    const int tid = threadIdx.x;
    const int b   = blockIdx.x;
    const int r   = tid >> 1;
    const int hf  = tid & 1;
    const int k0  = hf << 7;

    for (int idx = tid; idx < 96*256; idx += 512) {
        int jp = idx >> 8, rr = idx & 255;
        int k = (jp < 48) ? jp : (128 + jp - 48);
        Ws[jp*256 + rr] = W_hh[rr*256 + k];
    }
    float Wr[80];
#pragma unroll
    for (int i = 0; i < 80; i++) Wr[i] = W_hh[r*256 + k0 + 48 + i];
    if (tid < 256) hb0[tid] = prev_state[b*HDIM + tid];
    const float bhh = b_hh[r];
    __syncthreads();

    const float* Wsh   = Ws + (hf*48)*256 + r;     // Wsh[j*256] = W[r][k0+j]
    const float* xbase = g_xproj + (size_t)b * TSTEPS * HDIM + r;
    float*       gout  = g_hcap  + (size_t)b * TSTEPS * HDIM + r;

    const float* cur = hb0;
    float*       nxt = hb1;

#pragma unroll 1
    for (int s = 0; s < TSTEPS; s++) {
        float xp = 0.f;
        if (hf == 0) xp = xbase[s * HDIM];   // prefetch early; used after reduce
        float acc = 0.f;
#pragma unroll
        for (int jq = 0; jq < 12; jq++) {
            float4 h4 = *(const float4*)(cur + k0 + jq*4);
            acc += Wsh[(jq*4+0)*256] * h4.x;
            acc += Wsh[(jq*4+1)*256] * h4.y;
            acc += Wsh[(jq*4+2)*256] * h4.z;
            acc += Wsh[(jq*4+3)*256] * h4.w;
        }
#pragma unroll
        for (int iq = 0; iq < 20; iq++) {
            float4 h4 = *(const float4*)(cur + k0 + 48 + iq*4);
            acc += Wr[iq*4+0] * h4.x;
            acc += Wr[iq*4+1] * h4.y;
            acc += Wr[iq*4+2] * h4.z;
            acc += Wr[iq*4+3] * h4.w;
        }
        acc += __shfl_xor_sync(0xffffffffu, acc, 1);
        if (hf == 0) {
            float h = fmaxf(xp + acc + bhh, 0.f);
            nxt[r] = h;
            gout[s * HDIM] = fminf(h, 1.f);   // capped lrelu (h >= 0)
            if (s == TSTEPS - 1) hn_out[b*HDIM + r] = h;
        }
        __syncthreads();
        float* t = nxt; nxt = (float*)cur; cur = t;
    }
}

// ---------------------------------------------------------------------------
extern "C" void kernel_launch(void* const* d_in, const int* in_sizes, int n_in,
                              void* d_out, int out_size)
{
    const float* sentence   = (const float*)d_in[0];
    const float* prev_state = (const float*)d_in[1];
    const float* W_ih  = (const float*)d_in[2];
    const float* b_ih  = (const float*)d_in[3];
    const float* W_hh  = (const float*)d_in[4];
    const float* b_hh  = (const float*)d_in[5];
    const float* W_out = (const float*)d_in[6];
    const float* b_out = (const float*)d_in[7];

    float* tags = (float*)d_out;                                   // [B,T,O]
    float* hn   = tags + (size_t)NBATCH * TSTEPS * ODIM;           // [1,B,H]

    void* xp_ptr = nullptr; cudaGetSymbolAddress(&xp_ptr, g_xproj);
    void* hc_ptr = nullptr; cudaGetSymbolAddress(&hc_ptr, g_hcap);

    // K1: x_proj = sentence @ W_ih^T + b_ih
    gemm_nt_kernel<HDIM, VDIM, false>
        <<<dim3(HDIM/64, BT_TOTAL/128), 256>>>(sentence, W_ih, b_ih, (float*)xp_ptr);

    // K2: serial recurrence (also writes h_n and capped activations)
    const int rnn_smem = (96*256 + 2*HDIM) * 4;
    cudaFuncSetAttribute(rnn_recurrence_kernel,
                         cudaFuncAttributeMaxDynamicSharedMemorySize, rnn_smem);
    rnn_recurrence_kernel<<<NBATCH, 512, rnn_smem>>>(prev_state, W_hh, b_hh, hn);

    // K3: tags = sigmoid(capped @ W_out^T + b_out)
    gemm_nt_kernel<ODIM, HDIM, true>
        <<<dim3(ODIM/64, BT_TOTAL/128), 256>>>((const float*)hc_ptr, W_out, b_out, tags);
}

// round 7
// speedup vs baseline: 1.2556x; 1.2556x over previous
#include <cuda_runtime.h>
#include <math.h>

#define NBATCH   64
#define TSTEPS   512
#define VDIM     512
#define HDIM     256
#define ODIM     512
#define BT_TOTAL (NBATCH * TSTEPS)   // 32768

// Scratch (device globals: no allocation allowed)
__device__ float g_xproj[(size_t)BT_TOTAL * HDIM];  // x @ W_ih^T + b_ih
__device__ float g_hcap [(size_t)BT_TOTAL * HDIM];  // min(h_t, 1)

// ---- packed f32x2 helpers (sm_103a; ptxas won't emit FFMA2 from C++) ----
#define FMA2(d, a, b) \
    asm("fma.rn.f32x2 %0, %1, %2, %0;" : "+l"(d) : "l"(a), "l"(b))
#define ADD2(d, a, b) \
    asm("add.rn.f32x2 %0, %1, %2;" : "=l"(d) : "l"(a), "l"(b))
#define PACKDUP(d, s) \
    asm("mov.b64 %0, {%1, %1};" : "=l"(d) : "f"(s))
#define PACK2(d, x, y) \
    asm("mov.b64 %0, {%1, %2};" : "=l"(d) : "f"(x), "f"(y))
#define UNPACK2(x, y, s) \
    asm("mov.b64 {%0, %1}, %2;" : "=f"(x), "=f"(y) : "l"(s))

// ---------------------------------------------------------------------------
// NT SGEMM, f32x2 packed: C[M,N] = A[M,K]*B[N,K]^T + bias (+sigmoid).
// BM=128, BN=128, BK=16, 256 threads, 8x8 per-thread tile.
// Accumulators packed over m-pairs: A operand read as u64 pairs from SMEM.
// ---------------------------------------------------------------------------
template<int N, int K, bool SIG>
__global__ __launch_bounds__(256) void gemm2_kernel(
    const float* __restrict__ A, const float* __restrict__ Bw,
    const float* __restrict__ bias, float* __restrict__ C)
{
    __shared__ float As[16][128];
    __shared__ float Bs[16][128];
    const int tid = threadIdx.x;
    const int tx = tid & 15;      // n: 16 * 8 = 128
    const int ty = tid >> 4;      // m: 16 * 8 = 128
    const int m0 = blockIdx.y * 128;
    const int n0 = blockIdx.x * 128;

    unsigned long long acc[4][8];   // [m-pair][n] ; u64 0 == {0.f,0.f}
#pragma unroll
    for (int i = 0; i < 4; i++)
#pragma unroll
        for (int j = 0; j < 8; j++) acc[i][j] = 0ull;

#pragma unroll 1
    for (int kt = 0; kt < K; kt += 16) {
#pragma unroll
        for (int i = 0; i < 2; i++) {
            int idx = tid + i * 256;          // 512 float4 = 128 rows x 16 k
            int m = idx >> 2, kq = idx & 3;
            float4 f = *(const float4*)(A + (size_t)(m0 + m) * K + kt + kq * 4);
            As[kq*4+0][m] = f.x; As[kq*4+1][m] = f.y;
            As[kq*4+2][m] = f.z; As[kq*4+3][m] = f.w;
            float4 g = *(const float4*)(Bw + (size_t)(n0 + m) * K + kt + kq * 4);
            Bs[kq*4+0][m] = g.x; Bs[kq*4+1][m] = g.y;
            Bs[kq*4+2][m] = g.z; Bs[kq*4+3][m] = g.w;
        }
        __syncthreads();
#pragma unroll
        for (int k = 0; k < 16; k++) {
            const unsigned long long* ap =
                (const unsigned long long*)&As[k][ty*8];   // 4 m-pairs
            float4 b0 = *(const float4*)&Bs[k][tx*8];
            float4 b1 = *(const float4*)&Bs[k][tx*8+4];
            unsigned long long av[4];
#pragma unroll
            for (int i = 0; i < 4; i++) av[i] = ap[i];
            unsigned long long bb[8];
            PACKDUP(bb[0], b0.x); PACKDUP(bb[1], b0.y);
            PACKDUP(bb[2], b0.z); PACKDUP(bb[3], b0.w);
            PACKDUP(bb[4], b1.x); PACKDUP(bb[5], b1.y);
            PACKDUP(bb[6], b1.z); PACKDUP(bb[7], b1.w);
#pragma unroll
            for (int i = 0; i < 4; i++)
#pragma unroll
                for (int j = 0; j < 8; j++)
                    FMA2(acc[i][j], av[i], bb[j]);
        }
        __syncthreads();
    }

    float4 bv0 = *(const float4*)(bias + n0 + tx*8);
    float4 bv1 = *(const float4*)(bias + n0 + tx*8 + 4);
    float bb[8] = {bv0.x,bv0.y,bv0.z,bv0.w,bv1.x,bv1.y,bv1.z,bv1.w};
#pragma unroll
    for (int i = 0; i < 4; i++) {
        float lo[8], hi[8];
#pragma unroll
        for (int j = 0; j < 8; j++) UNPACK2(lo[j], hi[j], acc[i][j]);
        int m = m0 + ty*8 + 2*i;
#pragma unroll
        for (int h = 0; h < 2; h++) {
            float* row = h ? hi : lo;
            float v[8];
#pragma unroll
            for (int j = 0; j < 8; j++) {
                float x = row[j] + bb[j];
                if (SIG) x = __fdividef(1.f, 1.f + __expf(-x));
                v[j] = x;
            }
            float4 r0; r0.x=v[0]; r0.y=v[1]; r0.z=v[2]; r0.w=v[3];
            float4 r1; r1.x=v[4]; r1.y=v[5]; r1.z=v[6]; r1.w=v[7];
            *(float4*)(C + (size_t)(m + h) * N + n0 + tx*8)     = r0;
            *(float4*)(C + (size_t)(m + h) * N + n0 + tx*8 + 4) = r1;
        }
    }
}

// ---------------------------------------------------------------------------
// Recurrence v2 (f32x2): one CTA per batch, 512 threads. Thread (r, hf)
// computes row r over k in [hf*128, hf*128+128) as 64 packed pairs:
// 24 pairs from SMEM (Ws[j][tid], conflict-free LDS.64) + 40 pairs in RF.
// 4 independent packed accumulator chains; pair-reduce via shuffle.
// ---------------------------------------------------------------------------
__global__ __launch_bounds__(512) void rnn2_kernel(
    const float* __restrict__ prev_state,
    const float* __restrict__ W_hh,
    const float* __restrict__ b_hh,
    float* __restrict__ hn_out)
{
    extern __shared__ float sm[];
    unsigned long long* Ws = (unsigned long long*)sm;  // [24][512] u64 = 96 KB
    float* hb0 = sm + 24*512*2;    // (u64 = 2 floats)
    float* hb1 = hb0 + 256;

    const int tid = threadIdx.x;
    const int b   = blockIdx.x;
    const int r   = tid >> 1;
    const int hf  = tid & 1;
    const int k0  = hf << 7;

    // W pairs for this thread: wrow[j] = (W[r][k0+2j], W[r][k0+2j+1])
    const float2* wrow = (const float2*)(W_hh + r*HDIM + k0);
#pragma unroll
    for (int j = 0; j < 24; j++) {
        float2 w = wrow[j];
        unsigned long long u; PACK2(u, w.x, w.y);
        Ws[j*512 + tid] = u;                  // k = k0 + 2j, 2j+1
    }
    unsigned long long Wr[40];
#pragma unroll
    for (int i = 0; i < 40; i++) {
        float2 w = wrow[24 + i];              // k = k0 + 48 + 2i
        PACK2(Wr[i], w.x, w.y);
    }
    if (tid < 256) hb0[tid] = prev_state[b*HDIM + tid];
    const float bhh = b_hh[r];
    __syncthreads();

    const float* xbase = g_xproj + (size_t)b * TSTEPS * HDIM + r;
    float*       gout  = g_hcap  + (size_t)b * TSTEPS * HDIM + r;
    const unsigned long long* wsp = Ws + tid;

    const float* cur = hb0;
    float*       nxt = hb1;

#pragma unroll 1
    for (int s = 0; s < TSTEPS; s++) {
        float xp = 0.f;
        if (hf == 0) xp = xbase[s * HDIM];    // early gmem prefetch
        unsigned long long a0 = 0ull, a1 = 0ull, a2 = 0ull, a3 = 0ull;

        const ulonglong2* hA = (const ulonglong2*)(cur + k0);        // k0..k0+47
        const ulonglong2* hB = (const ulonglong2*)(cur + k0 + 48);   // k0+48..k0+127
#pragma unroll
        for (int q = 0; q < 12; q++) {        // 24 SMEM pairs
            ulonglong2 hv = hA[q];
            FMA2(a0, wsp[(2*q  )*512], hv.x);
            FMA2(a1, wsp[(2*q+1)*512], hv.y);
        }
#pragma unroll
        for (int q = 0; q < 20; q++) {        // 40 RF pairs
            ulonglong2 hv = hB[q];
            FMA2(a2, Wr[2*q  ], hv.x);
            FMA2(a3, Wr[2*q+1], hv.y);
        }
        ADD2(a0, a0, a1);
        ADD2(a2, a2, a3);
        ADD2(a0, a0, a2);
        float lo, hi; UNPACK2(lo, hi, a0);
        float sum = lo + hi;
        sum += __shfl_xor_sync(0xffffffffu, sum, 1);
        if (hf == 0) {
            float h = fmaxf(xp + sum + bhh, 0.f);
            nxt[r] = h;
            gout[s * HDIM] = fminf(h, 1.f);   // capped lrelu (h >= 0)
            if (s == TSTEPS - 1) hn_out[b*HDIM + r] = h;
        }
        __syncthreads();
        float* t = nxt; nxt = (float*)cur; cur = t;
    }
}

// ---------------------------------------------------------------------------
extern "C" void kernel_launch(void* const* d_in, const int* in_sizes, int n_in,
                              void* d_out, int out_size)
{
    const float* sentence   = (const float*)d_in[0];
    const float* prev_state = (const float*)d_in[1];
    const float* W_ih  = (const float*)d_in[2];
    const float* b_ih  = (const float*)d_in[3];
    const float* W_hh  = (const float*)d_in[4];
    const float* b_hh  = (const float*)d_in[5];
    const float* W_out = (const float*)d_in[6];
    const float* b_out = (const float*)d_in[7];

    float* tags = (float*)d_out;                                   // [B,T,O]
    float* hn   = tags + (size_t)NBATCH * TSTEPS * ODIM;           // [1,B,H]

    void* xp_ptr = nullptr; cudaGetSymbolAddress(&xp_ptr, g_xproj);
    void* hc_ptr = nullptr; cudaGetSymbolAddress(&hc_ptr, g_hcap);

    // K1: x_proj = sentence @ W_ih^T + b_ih
    gemm2_kernel<HDIM, VDIM, false>
        <<<dim3(HDIM/128, BT_TOTAL/128), 256>>>(sentence, W_ih, b_ih, (float*)xp_ptr);

    // K2: serial recurrence (writes h_n and capped activations)
    const int rnn_smem = 24*512*8 + 2*HDIM*4;   // 96 KB Ws + 2 h buffers
    cudaFuncSetAttribute(rnn2_kernel,
                         cudaFuncAttributeMaxDynamicSharedMemorySize, rnn_smem);
    rnn2_kernel<<<NBATCH, 512, rnn_smem>>>(prev_state, W_hh, b_hh, hn);

    // K3: tags = sigmoid(capped @ W_out^T + b_out)
    gemm2_kernel<ODIM, HDIM, true>
        <<<dim3(ODIM/128, BT_TOTAL/128), 256>>>((const float*)hc_ptr, W_out, b_out, tags);
}